// round 9
// baseline (speedup 1.0000x reference)
#include <cuda_runtime.h>
#include <cstdint>

#define Bv   32
#define Tv   168
#define NHv  32
#define NMv  64
#define Ev   384
#define HGv  64
#define HLv  128
#define G4   512
#define FUT  24
#define GT   (Bv*Tv)

#define RES   104        // Whh rows resident in smem (kC)
#define NREG  24         // Whh rows resident in registers (kC)

// -------- scratch --------
__device__ float d_gnnh[(size_t)NHv * Tv * Bv * HGv];     // [s][t][b][k]
__device__ float d_whhT[(size_t)NHv * HLv * G4];          // [s][k][j]
__device__ float d_wihT[(size_t)NHv * HGv * G4];          // [s][k][j]
__device__ float d_bsum[NHv * G4];
__device__ float d_xproj[(size_t)NHv * 4 * Tv * G4 * 8];  // [(s*4+bg)][t][j][bi]
__device__ float d_hfin[NHv * Bv * HLv];                  // [s][b][n]
__device__ int   d_edges[2 * Ev];

typedef unsigned long long u64t;

__device__ __forceinline__ u64t pk2(float x, float y) {
    u64t r; asm("mov.b64 %0,{%1,%2};" : "=l"(r) : "f"(x), "f"(y)); return r;
}
__device__ __forceinline__ float2 up2(u64t v) {
    float2 f; asm("mov.b64 {%0,%1},%2;" : "=f"(f.x), "=f"(f.y) : "l"(v)); return f;
}
__device__ __forceinline__ u64t fma2(u64t a, u64t b, u64t c) {
    u64t r; asm("fma.rn.f32x2 %0,%1,%2,%3;" : "=l"(r) : "l"(a), "l"(b), "l"(c)); return r;
}
__device__ __forceinline__ float sigf(float x) {
    return __fdividef(1.0f, 1.0f + __expf(-x));
}
__device__ __forceinline__ float tanhfast(float x) {
    return 1.0f - 2.0f * __fdividef(1.0f, __expf(2.0f * x) + 1.0f);
}
__device__ __forceinline__ float lrelu(float v) { return v > 0.0f ? v : 0.01f * v; }

// =====================================================================
// kE: dtype-robust edge decode (int64 vs silently-int32 edge_index)
// =====================================================================
__global__ void kE(const void* __restrict__ ei) {
    __shared__ int nz;
    const int* w = (const int*)ei;
    if (threadIdx.x == 0) nz = 0;
    __syncthreads();
    int cnt = 0;
    for (int i = threadIdx.x; i < 2 * Ev; i += blockDim.x)
        if ((i & 1) && w[i] == 0) cnt++;
    for (int o = 16; o > 0; o >>= 1) cnt += __shfl_down_sync(0xffffffffu, cnt, o);
    if ((threadIdx.x & 31) == 0) atomicAdd(&nz, cnt);
    __syncthreads();
    bool is64 = (nz > 100);
    for (int i = threadIdx.x; i < 2 * Ev; i += blockDim.x)
        d_edges[i] = is64 ? (int)((const long long*)ei)[i] : w[i];
}

// =====================================================================
// kA: GNN per graph g = b*Tv + t. Output [s][t][b][k]. smem atomics for agg.
// =====================================================================
__global__ void __launch_bounds__(128) kA(
        const float* __restrict__ hyd, const float* __restrict__ met,
        const float* __restrict__ Wr, const float* __restrict__ Wl,
        const float* __restrict__ bg) {
    __shared__ float xv[96], agg[NHv], wr[HGv], wl[HGv], bb[HGv];
    int g = blockIdx.x;
    int t = g % Tv, b = g / Tv;
    int tid = threadIdx.x;

    if (tid < NHv) { xv[tid] = hyd[(size_t)g * NHv + tid]; agg[tid] = 0.0f; }
    if (tid >= 32 && tid < 96) xv[tid] = met[(size_t)g * NMv + (tid - 32)];
    if (tid < HGv) { wr[tid] = Wr[tid]; wl[tid] = Wl[tid]; bb[tid] = bg[tid]; }
    __syncthreads();

    #pragma unroll
    for (int r = 0; r < 3; r++) {
        int e = tid + r * 128;
        int dn = d_edges[Ev + e];
        if (dn < NHv) atomicAdd(&agg[dn], xv[d_edges[e]]);
    }
    __syncthreads();

    #pragma unroll
    for (int i = 0; i < 16; i++) {
        int idx = tid + i * 128;
        int s = idx >> 6, k = idx & 63;
        float v = xv[s] * wr[k] + agg[s] * wl[k] + bb[k];
        d_gnnh[(((size_t)s * Tv + t) * Bv + b) * HGv + k] = lrelu(v);
    }
}

// =====================================================================
// kT: tiled per-station transpose [s][J][K] -> [s][K][J]. which: 0=whh,1=wih
// =====================================================================
__global__ void kT(const float* __restrict__ src, int J, int K, int which) {
    __shared__ float tile[32][33];
    int s = blockIdx.z;
    int k0 = blockIdx.x * 32, j0 = blockIdx.y * 32;
    int tx = threadIdx.x, ty = threadIdx.y;
    const float* S = src + (size_t)s * J * K;
    float* D = (which == 0 ? d_whhT : d_wihT) + (size_t)s * J * K;
    #pragma unroll
    for (int dy = 0; dy < 32; dy += 8)
        tile[ty + dy][tx] = S[(size_t)(j0 + ty + dy) * K + (k0 + tx)];
    __syncthreads();
    #pragma unroll
    for (int dy = 0; dy < 32; dy += 8)
        D[(size_t)(k0 + ty + dy) * J + (j0 + tx)] = tile[tx][ty + dy];
}

__global__ void kBias(const float* __restrict__ bih, const float* __restrict__ bhh) {
    int s = blockIdx.x, j = threadIdx.x;
    d_bsum[s * G4 + j] = bih[s * G4 + j] + bhh[s * G4 + j];
}

// =====================================================================
// kB: input projection. grid (t, s, z), 128 threads; thread jj: 4 j's, 16 b.
// =====================================================================
__global__ void __launch_bounds__(128) kB() {
    int t = blockIdx.x, s = blockIdx.y, z = blockIdx.z;
    int jj = threadIdx.x;
    int j0 = jj * 4;
    __shared__ float hloc[64 * 20];  // [k][b16], pad to 20

    {
        const float* src = &d_gnnh[(((size_t)s * Tv + t) * Bv + z * 16) * HGv];
        #pragma unroll
        for (int r = 0; r < 2; r++) {
            int id = jj + r * 128;
            float4 v = reinterpret_cast<const float4*>(src)[id];
            int b = id >> 4, k0 = (id & 15) * 4;
            hloc[(k0 + 0) * 20 + b] = v.x;
            hloc[(k0 + 1) * 20 + b] = v.y;
            hloc[(k0 + 2) * 20 + b] = v.z;
            hloc[(k0 + 3) * 20 + b] = v.w;
        }
    }
    __syncthreads();

    u64t acc[4][8];
    {
        float4 bb = *reinterpret_cast<const float4*>(&d_bsum[s * G4 + j0]);
        float bv[4] = {bb.x, bb.y, bb.z, bb.w};
        #pragma unroll
        for (int jl = 0; jl < 4; jl++) {
            u64t b2 = pk2(bv[jl], bv[jl]);
            #pragma unroll
            for (int q = 0; q < 8; q++) acc[jl][q] = b2;
        }
    }

    const float* wT = d_wihT + (size_t)s * (HGv * G4);
    #pragma unroll 2
    for (int k = 0; k < 64; k++) {
        float4 w = *reinterpret_cast<const float4*>(&wT[k * G4 + j0]);
        float wv[4] = {w.x, w.y, w.z, w.w};
        const ulonglong2* hp = reinterpret_cast<const ulonglong2*>(&hloc[k * 20]);
        ulonglong2 h0 = hp[0], h1 = hp[1], h2 = hp[2], h3 = hp[3];
        #pragma unroll
        for (int jl = 0; jl < 4; jl++) {
            u64t W = pk2(wv[jl], wv[jl]);
            acc[jl][0] = fma2(h0.x, W, acc[jl][0]);
            acc[jl][1] = fma2(h0.y, W, acc[jl][1]);
            acc[jl][2] = fma2(h1.x, W, acc[jl][2]);
            acc[jl][3] = fma2(h1.y, W, acc[jl][3]);
            acc[jl][4] = fma2(h2.x, W, acc[jl][4]);
            acc[jl][5] = fma2(h2.y, W, acc[jl][5]);
            acc[jl][6] = fma2(h3.x, W, acc[jl][6]);
            acc[jl][7] = fma2(h3.y, W, acc[jl][7]);
        }
    }

    #pragma unroll
    for (int jl = 0; jl < 4; jl++) {
        #pragma unroll
        for (int half = 0; half < 2; half++) {
            float* base = &d_xproj[(((size_t)(s * 4 + z * 2 + half) * Tv + t) * G4
                                    + (j0 + jl)) * 8];
            ulonglong2 v0, v1;
            v0.x = acc[jl][half * 4 + 0]; v0.y = acc[jl][half * 4 + 1];
            v1.x = acc[jl][half * 4 + 2]; v1.y = acc[jl][half * 4 + 3];
            reinterpret_cast<ulonglong2*>(base)[0] = v0;
            reinterpret_cast<ulonglong2*>(base)[1] = v1;
        }
    }
}

// =====================================================================
// kC: recurrence. 128 blocks = (s, bg), 256 threads.
// Warp w covers units n in [16w, 16w+16) x batch-halves bh in {0,1}
// (lane = bh*16 + nlo) -> both bh lanes read the SAME weight float4 =>
// smem broadcast dedup halves crossbar traffic (2048 B/warp-step -> 256 B/k).
// Thread owns gates {n,+128,+256,+384} x 4 batches: gate update thread-local.
// Whh: RES rows packed in smem [k][n][4g], NREG rows in registers.
// =====================================================================
#define SMEM_C (RES * G4 * 4 + 2 * 1024 * 4)

extern __shared__ float smc[];

__global__ void __launch_bounds__(256) kC() {
    int blk = blockIdx.x;
    int s = blk >> 2, bg = blk & 3;
    int tid = threadIdx.x;
    int w = tid >> 5, l = tid & 31;
    int n = w * 16 + (l & 15);   // hidden unit
    int bh = l >> 4;             // batch half: batches bh*4 .. bh*4+3

    float* wpk = smc;                   // [RES][128n][4g] packed
    float* hb0 = smc + RES * G4;        // [128n][8bi] double buffer
    float* hb1 = hb0 + 1024;

    const float* whhTs = d_whhT + (size_t)s * (HLv * G4);
    // pack: wpk[k*512 + nn*4 + g] = whhT[k][g*128 + nn]
    for (int i = tid; i < RES * G4; i += 256) {
        int k = i >> 9, q = i & 511;
        int nn = q >> 2, g = q & 3;
        wpk[i] = whhTs[(size_t)k * G4 + g * 128 + nn];
    }
    for (int i = tid; i < 1024; i += 256) hb0[i] = 0.0f;

    float wreg[NREG][4];
    #pragma unroll
    for (int r = 0; r < NREG; r++)
        #pragma unroll
        for (int g = 0; g < 4; g++)
            wreg[r][g] = whhTs[(size_t)(RES + r) * G4 + g * 128 + n];

    float c[4];
    #pragma unroll
    for (int q = 0; q < 4; q++) c[q] = 0.0f;

    const float* xp = d_xproj + (size_t)(s * 4 + bg) * Tv * (G4 * 8);
    float4 xc[4];
    #pragma unroll
    for (int g = 0; g < 4; g++)
        xc[g] = *reinterpret_cast<const float4*>(xp + (size_t)(n + g * 128) * 8 + bh * 4);

    float* hcur = hb0;
    float* hnxt = hb1;
    __syncthreads();

    for (int t = 0; t < Tv; t++) {
        u64t acc[8];
        #pragma unroll
        for (int g = 0; g < 4; g++) {
            acc[2 * g + 0] = pk2(xc[g].x, xc[g].y);
            acc[2 * g + 1] = pk2(xc[g].z, xc[g].w);
        }
        if (t < Tv - 1) {
            const float* xn = xp + (size_t)(t + 1) * (G4 * 8);
            #pragma unroll
            for (int g = 0; g < 4; g++)
                xc[g] = *reinterpret_cast<const float4*>(
                    xn + (size_t)(n + g * 128) * 8 + bh * 4);
        }

        #pragma unroll 4
        for (int k = 0; k < RES; k++) {
            float4 wv = *reinterpret_cast<const float4*>(&wpk[k * G4 + n * 4]);
            ulonglong2 h = *reinterpret_cast<const ulonglong2*>(&hcur[k * 8 + bh * 4]);
            u64t W;
            W = pk2(wv.x, wv.x);
            acc[0] = fma2(h.x, W, acc[0]); acc[1] = fma2(h.y, W, acc[1]);
            W = pk2(wv.y, wv.y);
            acc[2] = fma2(h.x, W, acc[2]); acc[3] = fma2(h.y, W, acc[3]);
            W = pk2(wv.z, wv.z);
            acc[4] = fma2(h.x, W, acc[4]); acc[5] = fma2(h.y, W, acc[5]);
            W = pk2(wv.w, wv.w);
            acc[6] = fma2(h.x, W, acc[6]); acc[7] = fma2(h.y, W, acc[7]);
        }
        #pragma unroll
        for (int r = 0; r < NREG; r++) {
            int k = RES + r;
            ulonglong2 h = *reinterpret_cast<const ulonglong2*>(&hcur[k * 8 + bh * 4]);
            u64t W;
            W = pk2(wreg[r][0], wreg[r][0]);
            acc[0] = fma2(h.x, W, acc[0]); acc[1] = fma2(h.y, W, acc[1]);
            W = pk2(wreg[r][1], wreg[r][1]);
            acc[2] = fma2(h.x, W, acc[2]); acc[3] = fma2(h.y, W, acc[3]);
            W = pk2(wreg[r][2], wreg[r][2]);
            acc[4] = fma2(h.x, W, acc[4]); acc[5] = fma2(h.y, W, acc[5]);
            W = pk2(wreg[r][3], wreg[r][3]);
            acc[6] = fma2(h.x, W, acc[6]); acc[7] = fma2(h.y, W, acc[7]);
        }

        // thread-local gate update: acc[0,1]=i, [2,3]=f, [4,5]=g, [6,7]=o
        {
            float2 i0 = up2(acc[0]), i1 = up2(acc[1]);
            float2 f0 = up2(acc[2]), f1 = up2(acc[3]);
            float2 g0 = up2(acc[4]), g1 = up2(acc[5]);
            float2 o0 = up2(acc[6]), o1 = up2(acc[7]);
            float4 hv;
            c[0] = sigf(f0.x) * c[0] + sigf(i0.x) * tanhfast(g0.x);
            hv.x = sigf(o0.x) * tanhfast(c[0]);
            c[1] = sigf(f0.y) * c[1] + sigf(i0.y) * tanhfast(g0.y);
            hv.y = sigf(o0.y) * tanhfast(c[1]);
            c[2] = sigf(f1.x) * c[2] + sigf(i1.x) * tanhfast(g1.x);
            hv.z = sigf(o1.x) * tanhfast(c[2]);
            c[3] = sigf(f1.y) * c[3] + sigf(i1.y) * tanhfast(g1.y);
            hv.w = sigf(o1.y) * tanhfast(c[3]);
            *reinterpret_cast<float4*>(&hnxt[n * 8 + bh * 4]) = hv;
        }
        __syncthreads();
        float* tmp = hcur; hcur = hnxt; hnxt = tmp;
    }

    #pragma unroll
    for (int q = 0; q < 4; q++) {
        int b = bg * 8 + bh * 4 + q;
        d_hfin[((size_t)s * Bv + b) * HLv + n] = hcur[n * 8 + bh * 4 + q];
    }
}

// =====================================================================
// kD: final linear + lrelu
// =====================================================================
__global__ void kD(const float* __restrict__ wlin, const float* __restrict__ blin,
                   float* __restrict__ out) {
    int s = blockIdx.x >> 5, b = blockIdx.x & 31;
    int f = threadIdx.x;
    __shared__ float hs[HLv];
    for (int i = threadIdx.x; i < HLv; i += 32)
        hs[i] = d_hfin[((size_t)s * Bv + b) * HLv + i];
    __syncthreads();
    if (f < FUT) {
        float a = blin[f];
        #pragma unroll 8
        for (int k = 0; k < HLv; k++) a += hs[k] * wlin[f * HLv + k];
        out[((size_t)b * NHv + s) * FUT + f] = lrelu(a);
    }
}

// =====================================================================
extern "C" void kernel_launch(void* const* d_in, const int* in_sizes, int n_in,
                              void* d_out, int out_size) {
    const float* meteo = (const float*)d_in[0];
    const float* hydro = (const float*)d_in[1];
    if (in_sizes[0] == Bv * Tv * NHv) {
        hydro = (const float*)d_in[0];
        meteo = (const float*)d_in[1];
    }
    const void*  ei    = d_in[2];
    const float* Wr    = (const float*)d_in[3];
    const float* Wl    = (const float*)d_in[4];
    const float* bgnn  = (const float*)d_in[5];
    const float* Wih   = (const float*)d_in[6];
    const float* Whh   = (const float*)d_in[7];
    if (in_sizes[6] == NHv * G4 * HLv) {
        Whh = (const float*)d_in[6];
        Wih = (const float*)d_in[7];
    }
    const float* bih   = (const float*)d_in[8];
    const float* bhh   = (const float*)d_in[9];
    const float* Wlin  = (const float*)d_in[10];
    const float* blin  = (const float*)d_in[11];
    float* out = (float*)d_out;

    cudaFuncSetAttribute(kC, cudaFuncAttributeMaxDynamicSharedMemorySize, SMEM_C);

    kE<<<1, 256>>>(ei);
    kA<<<GT, 128>>>(hydro, meteo, Wr, Wl, bgnn);
    kT<<<dim3(4, 16, NHv), dim3(32, 8)>>>(Whh, G4, HLv, 0);
    kT<<<dim3(2, 16, NHv), dim3(32, 8)>>>(Wih, G4, HGv, 1);
    kBias<<<NHv, 512>>>(bih, bhh);
    kB<<<dim3(Tv, NHv, 2), 128>>>();
    kC<<<128, 256, SMEM_C>>>();
    kD<<<NHv * Bv, 32>>>(Wlin, blin, out);
}